// round 9
// baseline (speedup 1.0000x reference)
#include <cuda_runtime.h>
#include <cuda_fp16.h>
#include <math.h>

// ---------------------------------------------------------------------------
// VariationalLinear fused kernel, round 9 (sm_100a)
//   out(256,4096) = x @ W^T + b,  W = mu + softplus(rho)*eps_w, + analytic KL
//   (prior_mu=0, prior_sigma=0.1 folded as constants; validated R8)
//
// R9 vs R8 (85.9us; latency-bound at 16 warps/SM, occ 21%, all pipes <45%):
//  - 512 threads/CTA, warp owns M=16 rows -> acc 64->32 regs, Wgen 2 els/thr
//  - __launch_bounds__(512,2) targets 64 regs -> 2 CTAs x 512 = 32 warps/SM
//  - identical pipeline skeleton: KC=16, raw 4 stages, X 2 stages, Wg double,
//    one __syncthreads per chunk, ldmatrix fragments, fp16 MMA / fp32 acc
// ---------------------------------------------------------------------------

#define BATCH   256
#define IN_F    4096
#define OUT_F   4096
#define NT      64
#define KSPLIT  4
#define KSEG    (IN_F / KSPLIT)    // 1024
#define KC      16
#define NCHUNK  (KSEG / KC)        // 64
#define XSTG    2
#define RSTG    4
#define XSH     24                 // X row stride (halves): 16 data + 8 pad
#define WSH     24                 // Wg row stride (halves)
#define THREADS 512

#define XS_BYTES  (BATCH * XSH * 2)     // 12288
#define RAW_FL    (3 * NT * KC)         // 3072 floats (mu, rho, epsw)
#define RAW_BYTES (RAW_FL * 4)          // 12288
#define WG_BYTES  (NT * WSH * 2)        // 3072
#define SMEM_BYTES (XSTG * XS_BYTES + RSTG * RAW_BYTES + 2 * WG_BYTES) // 79872

#define KL_C0  (-2.80258509299f)        // log(0.1) - 0.5

__device__ __align__(16) __half g_x_h[BATCH * IN_F];   // x in fp16, row-major

__device__ __forceinline__ void cp_async16(void* smem_dst, const void* gsrc) {
    unsigned saddr = (unsigned)__cvta_generic_to_shared(smem_dst);
    asm volatile("cp.async.cg.shared.global [%0], [%1], 16;"
                 :: "r"(saddr), "l"(gsrc));
}

__device__ __forceinline__ void ldsm_x4(unsigned& r0, unsigned& r1,
                                        unsigned& r2, unsigned& r3,
                                        unsigned saddr) {
    asm volatile("ldmatrix.sync.aligned.m8n8.x4.shared.b16 {%0,%1,%2,%3}, [%4];"
                 : "=r"(r0), "=r"(r1), "=r"(r2), "=r"(r3) : "r"(saddr));
}

__device__ __forceinline__ void mma_f16(float* c, const unsigned* a,
                                        unsigned b0, unsigned b1) {
    asm volatile(
        "mma.sync.aligned.m16n8k16.row.col.f32.f16.f16.f32 "
        "{%0,%1,%2,%3}, {%4,%5,%6,%7}, {%8,%9}, {%0,%1,%2,%3};"
        : "+f"(c[0]), "+f"(c[1]), "+f"(c[2]), "+f"(c[3])
        : "r"(a[0]), "r"(a[1]), "r"(a[2]), "r"(a[3]), "r"(b0), "r"(b1));
}

__device__ __forceinline__ float softplus_fast(float r) {
    return (r > 15.f) ? r : __logf(1.f + __expf(r));
}

// ---------------------------------------------------------------------------
// Prep: out <- bias broadcast, KL slot <- 0, x -> fp16 scratch.
// ---------------------------------------------------------------------------
__global__ void vl_prep(const float* __restrict__ x,
                        const float* __restrict__ bmu,
                        const float* __restrict__ brho,
                        const float* __restrict__ epsb,
                        float* __restrict__ out, int out_size) {
    int i = blockIdx.x * blockDim.x + threadIdx.x;
    if (i < BATCH * OUT_F) {
        int col = i & (OUT_F - 1);
        out[i] = fmaf(softplus_fast(brho[col]), epsb[col], bmu[col]);
    } else if (i < out_size) {
        out[i] = 0.f;
    }
    if (i < BATCH * IN_F)
        g_x_h[i] = __float2half_rn(x[i]);
}

// ---------------------------------------------------------------------------
// Main fused kernel: 512 threads, warp owns one m16 tile
// ---------------------------------------------------------------------------
__global__ void __launch_bounds__(THREADS, 2)
vl_main(const float* __restrict__ mu, const float* __restrict__ rho,
        const float* __restrict__ epsw,
        float* __restrict__ out, float* __restrict__ klout) {
    extern __shared__ char smbase[];
    __half* Xs  = (__half*)smbase;                               // [2][256][XSH]
    float*  Raw = (float*)(smbase + XSTG * XS_BYTES);            // [4][3][1024]
    __shared__ float klred[16];

    const unsigned sbase = (unsigned)__cvta_generic_to_shared(smbase);
    const unsigned xs_b  = sbase;
    const unsigned wg_b  = sbase + XSTG * XS_BYTES + RSTG * RAW_BYTES;

    const int tid  = threadIdx.x;
    const int warp = tid >> 5;                 // 0..15
    const int lane = tid & 31;
    const int g    = lane >> 2;
    const int t    = lane & 3;

    const int ntile = blockIdx.x >> 2;
    const int kseg  = blockIdx.x & 3;
    const int n0    = ntile * NT;
    const int kbase = kseg * KSEG;
    const int m16   = warp * 16;               // warp's M-row block

    float acc[8][4];
#pragma unroll
    for (int nt = 0; nt < 8; nt++)
#pragma unroll
        for (int i = 0; i < 4; i++) acc[nt][i] = 0.f;

    float klsum = 0.f;

    // Wgen: thread owns 2 consecutive elements of the 64x16 tile
    const int we   = tid * 2;                  // 0..1022
    const int wrow = we >> 4;                  // 0..63
    const int wk   = we & 15;
    // raw staging: 3 streams x 256 float4; f = tid (and tid+512 if tid<256)
    const int  rs0  = tid >> 8;                // stream of f=tid (tid<768)
    const int  ri0  = tid & 255;
    const long rg0  = (long)(n0 + (ri0 >> 2)) * IN_F + kbase + (ri0 & 3) * 4;
    const int  ri1  = (tid + 512) & 255;       // f=tid+512 -> stream 2 slice
    const long rg1  = (long)(n0 + (ri1 >> 2)) * IN_F + kbase + (ri1 & 3) * 4;
    const float* streams[3] = { mu, rho, epsw };

    // A ldmatrix offset (bytes): row = m16 + (lane&15), kofs = (lane>>4)*8
    const unsigned a_off =
        ((m16 + (lane & 15)) * XSH + ((lane >> 4) << 3)) * 2;
    // B ldmatrix base offset (pair p=0)
    const unsigned b_off0 =
        ((((lane >> 4) << 3) + (lane & 7)) * WSH + (((lane >> 3) & 1) << 3)) * 2;

    auto xPf = [&](int c) {                    // X chunk c -> stage c&1
        if (c < NCHUNK) {
            const int k0 = kbase + c * KC;
            __half* xd = Xs + (c & 1) * (BATCH * XSH);
            // 512 float4, one per thread
            int row = tid >> 1;
            int seg = tid & 1;
            cp_async16(xd + row * XSH + seg * 8,
                       g_x_h + (long)row * IN_F + k0 + seg * 8);
        }
        asm volatile("cp.async.commit_group;");
    };
    auto rPf = [&](int c) {                    // weights chunk c -> stage c%4
        if (c < NCHUNK) {
            float* rd = Raw + (c & 3) * RAW_FL;
            const int k0 = c * KC;
            if (tid < 768)
                cp_async16(rd + rs0 * (NT * KC) + ri0 * 4,
                           streams[rs0] + rg0 + k0);
            if (tid < 256)
                cp_async16(rd + 2 * (NT * KC) + ri1 * 4,
                           streams[2] + rg1 + k0);
        }
        asm volatile("cp.async.commit_group;");
    };

    // Wgen(k): raw stage k%4 -> Wg[k&1]; KL with prior constants folded
    auto wgen = [&](int k) {
        const float* rb = Raw + (k & 3) * RAW_FL;
        float2 m2 = *reinterpret_cast<const float2*>(rb + 0 * NT * KC + we);
        float2 r2 = *reinterpret_cast<const float2*>(rb + 1 * NT * KC + we);
        float2 e2 = *reinterpret_cast<const float2*>(rb + 2 * NT * KC + we);
        const float mv[2] = {m2.x, m2.y};
        const float rv[2] = {r2.x, r2.y};
        const float ev[2] = {e2.x, e2.y};
        float wv[2];
#pragma unroll
        for (int q = 0; q < 2; q++) {
            float sg = __logf(1.f + __expf(rv[q]));    // softplus
            wv[q] = fmaf(sg, ev[q], mv[q]);
            klsum += fmaf(50.f, fmaf(sg, sg, mv[q] * mv[q]),
                          KL_C0 - __logf(sg));
        }
        __half2 p0 = __floats2half2_rn(wv[0], wv[1]);
        *reinterpret_cast<__half2*>(
            (__half*)(smbase + XSTG * XS_BYTES + RSTG * RAW_BYTES)
            + (k & 1) * (NT * WSH) + wrow * WSH + wk) = p0;
    };

    // ---- prologue: groups [raw0][raw1][X0][raw2]; land raw0; Wgen(0) ----
    rPf(0);
    rPf(1);
    xPf(0);
    rPf(2);
    asm volatile("cp.async.wait_group 3;");
    __syncthreads();
    wgen(0);

    for (int c = 0; c < NCHUNK; c++) {
        asm volatile("cp.async.wait_group 1;");  // X(c), raw(c+1) landed
        __syncthreads();                         // one barrier per chunk

        xPf(c + 1);                              // stage (c+1)&1
        rPf(c + 3);                              // stage (c+3)&3

        if (c + 1 < NCHUNK) wgen(c + 1);         // -> Wg[(c+1)&1], overlaps MMA

        // ---- MMA(c): A (one m16 tile) + B via ldmatrix ----
        const unsigned xa = xs_b + (c & 1) * XS_BYTES + a_off;
        unsigned a0[4];
        ldsm_x4(a0[0], a0[1], a0[2], a0[3], xa);

        const unsigned wb = wg_b + (c & 1) * WG_BYTES + b_off0;
#pragma unroll
        for (int p = 0; p < 4; p++) {
            unsigned b0, b1, b2, b3;
            ldsm_x4(b0, b1, b2, b3, wb + p * 16 * WSH * 2);
            mma_f16(acc[2 * p],     a0, b0, b1);
            mma_f16(acc[2 * p + 1], a0, b2, b3);
        }
    }

    // ---- epilogue: atomic-accumulate partial output (bias already in out) ----
    {
        int r0 = m16 + g;
#pragma unroll
        for (int nt = 0; nt < 8; nt++) {
            int col = n0 + nt * 8 + 2 * t;
            atomicAdd(&out[(long)r0 * OUT_F + col],           acc[nt][0]);
            atomicAdd(&out[(long)r0 * OUT_F + col + 1],       acc[nt][1]);
            atomicAdd(&out[(long)(r0 + 8) * OUT_F + col],     acc[nt][2]);
            atomicAdd(&out[(long)(r0 + 8) * OUT_F + col + 1], acc[nt][3]);
        }
    }

    // ---- KL reduction ----
#pragma unroll
    for (int o = 16; o; o >>= 1)
        klsum += __shfl_xor_sync(0xFFFFFFFFu, klsum, o);
    if (lane == 0) klred[warp] = klsum;
    __syncthreads();
    if (tid == 0) {
        float s = 0.f;
#pragma unroll
        for (int i = 0; i < 16; i++) s += klred[i];
        atomicAdd(klout, s);
    }
}

// ---------------------------------------------------------------------------
extern "C" void kernel_launch(void* const* d_in, const int* in_sizes, int n_in,
                              void* d_out, int out_size) {
    const float* x    = (const float*)d_in[0];
    const float* wmu  = (const float*)d_in[1];
    const float* wrho = (const float*)d_in[2];
    const float* bmu  = (const float*)d_in[3];
    const float* brho = (const float*)d_in[4];
    const float* epsw = (const float*)d_in[5];
    const float* epsb = (const float*)d_in[6];
    float* out = (float*)d_out;

    int n = BATCH * IN_F;
    if (out_size > n) n = out_size;
    vl_prep<<<(n + 255) / 256, 256>>>(x, bmu, brho, epsb, out, out_size);

    cudaFuncSetAttribute(vl_main, cudaFuncAttributeMaxDynamicSharedMemorySize,
                         SMEM_BYTES);
    vl_main<<<(OUT_F / NT) * KSPLIT, THREADS, SMEM_BYTES>>>(
        wmu, wrho, epsw, out, out + (out_size - 1));
}

// round 10
// speedup vs baseline: 1.0067x; 1.0067x over previous
#include <cuda_runtime.h>
#include <cuda_fp16.h>
#include <math.h>

// ---------------------------------------------------------------------------
// VariationalLinear fused kernel, round 9 (sm_100a)
//   out(256,4096) = x @ W^T + b,  W = mu + softplus(rho)*eps_w, + analytic KL
//   (prior_mu=0, prior_sigma=0.1 folded as constants; validated R8)
//
// R9 vs R8 (85.9us; latency-bound at 16 warps/SM, occ 21%, all pipes <45%):
//  - 512 threads/CTA, warp owns M=16 rows -> acc 64->32 regs, Wgen 2 els/thr
//  - __launch_bounds__(512,2) targets 64 regs -> 2 CTAs x 512 = 32 warps/SM
//  - identical pipeline skeleton: KC=16, raw 4 stages, X 2 stages, Wg double,
//    one __syncthreads per chunk, ldmatrix fragments, fp16 MMA / fp32 acc
// ---------------------------------------------------------------------------

#define BATCH   256
#define IN_F    4096
#define OUT_F   4096
#define NT      64
#define KSPLIT  4
#define KSEG    (IN_F / KSPLIT)    // 1024
#define KC      16
#define NCHUNK  (KSEG / KC)        // 64
#define XSTG    2
#define RSTG    4
#define XSH     24                 // X row stride (halves): 16 data + 8 pad
#define WSH     24                 // Wg row stride (halves)
#define THREADS 512

#define XS_BYTES  (BATCH * XSH * 2)     // 12288
#define RAW_FL    (3 * NT * KC)         // 3072 floats (mu, rho, epsw)
#define RAW_BYTES (RAW_FL * 4)          // 12288
#define WG_BYTES  (NT * WSH * 2)        // 3072
#define SMEM_BYTES (XSTG * XS_BYTES + RSTG * RAW_BYTES + 2 * WG_BYTES) // 79872

#define KL_C0  (-2.80258509299f)        // log(0.1) - 0.5

__device__ __align__(16) __half g_x_h[BATCH * IN_F];   // x in fp16, row-major

__device__ __forceinline__ void cp_async16(void* smem_dst, const void* gsrc) {
    unsigned saddr = (unsigned)__cvta_generic_to_shared(smem_dst);
    asm volatile("cp.async.cg.shared.global [%0], [%1], 16;"
                 :: "r"(saddr), "l"(gsrc));
}

__device__ __forceinline__ void ldsm_x4(unsigned& r0, unsigned& r1,
                                        unsigned& r2, unsigned& r3,
                                        unsigned saddr) {
    asm volatile("ldmatrix.sync.aligned.m8n8.x4.shared.b16 {%0,%1,%2,%3}, [%4];"
                 : "=r"(r0), "=r"(r1), "=r"(r2), "=r"(r3) : "r"(saddr));
}

__device__ __forceinline__ void mma_f16(float* c, const unsigned* a,
                                        unsigned b0, unsigned b1) {
    asm volatile(
        "mma.sync.aligned.m16n8k16.row.col.f32.f16.f16.f32 "
        "{%0,%1,%2,%3}, {%4,%5,%6,%7}, {%8,%9}, {%0,%1,%2,%3};"
        : "+f"(c[0]), "+f"(c[1]), "+f"(c[2]), "+f"(c[3])
        : "r"(a[0]), "r"(a[1]), "r"(a[2]), "r"(a[3]), "r"(b0), "r"(b1));
}

__device__ __forceinline__ float softplus_fast(float r) {
    return (r > 15.f) ? r : __logf(1.f + __expf(r));
}

// ---------------------------------------------------------------------------
// Prep: out <- bias broadcast, KL slot <- 0, x -> fp16 scratch.
// ---------------------------------------------------------------------------
__global__ void vl_prep(const float* __restrict__ x,
                        const float* __restrict__ bmu,
                        const float* __restrict__ brho,
                        const float* __restrict__ epsb,
                        float* __restrict__ out, int out_size) {
    int i = blockIdx.x * blockDim.x + threadIdx.x;
    if (i < BATCH * OUT_F) {
        int col = i & (OUT_F - 1);
        out[i] = fmaf(softplus_fast(brho[col]), epsb[col], bmu[col]);
    } else if (i < out_size) {
        out[i] = 0.f;
    }
    if (i < BATCH * IN_F)
        g_x_h[i] = __float2half_rn(x[i]);
}

// ---------------------------------------------------------------------------
// Main fused kernel: 512 threads, warp owns one m16 tile
// ---------------------------------------------------------------------------
__global__ void __launch_bounds__(THREADS, 2)
vl_main(const float* __restrict__ mu, const float* __restrict__ rho,
        const float* __restrict__ epsw,
        float* __restrict__ out, float* __restrict__ klout) {
    extern __shared__ char smbase[];
    __half* Xs  = (__half*)smbase;                               // [2][256][XSH]
    float*  Raw = (float*)(smbase + XSTG * XS_BYTES);            // [4][3][1024]
    __shared__ float klred[16];

    const unsigned sbase = (unsigned)__cvta_generic_to_shared(smbase);
    const unsigned xs_b  = sbase;
    const unsigned wg_b  = sbase + XSTG * XS_BYTES + RSTG * RAW_BYTES;

    const int tid  = threadIdx.x;
    const int warp = tid >> 5;                 // 0..15
    const int lane = tid & 31;
    const int g    = lane >> 2;
    const int t    = lane & 3;

    const int ntile = blockIdx.x >> 2;
    const int kseg  = blockIdx.x & 3;
    const int n0    = ntile * NT;
    const int kbase = kseg * KSEG;
    const int m16   = warp * 16;               // warp's M-row block

    float acc[8][4];
#pragma unroll
    for (int nt = 0; nt < 8; nt++)
#pragma unroll
        for (int i = 0; i < 4; i++) acc[nt][i] = 0.f;

    float klsum = 0.f;

    // Wgen: thread owns 2 consecutive elements of the 64x16 tile
    const int we   = tid * 2;                  // 0..1022
    const int wrow = we >> 4;                  // 0..63
    const int wk   = we & 15;
    // raw staging: 3 streams x 256 float4; f = tid (and tid+512 if tid<256)
    const int  rs0  = tid >> 8;                // stream of f=tid (tid<768)
    const int  ri0  = tid & 255;
    const long rg0  = (long)(n0 + (ri0 >> 2)) * IN_F + kbase + (ri0 & 3) * 4;
    const int  ri1  = (tid + 512) & 255;       // f=tid+512 -> stream 2 slice
    const long rg1  = (long)(n0 + (ri1 >> 2)) * IN_F + kbase + (ri1 & 3) * 4;
    const float* streams[3] = { mu, rho, epsw };

    // A ldmatrix offset (bytes): row = m16 + (lane&15), kofs = (lane>>4)*8
    const unsigned a_off =
        ((m16 + (lane & 15)) * XSH + ((lane >> 4) << 3)) * 2;
    // B ldmatrix base offset (pair p=0)
    const unsigned b_off0 =
        ((((lane >> 4) << 3) + (lane & 7)) * WSH + (((lane >> 3) & 1) << 3)) * 2;

    auto xPf = [&](int c) {                    // X chunk c -> stage c&1
        if (c < NCHUNK) {
            const int k0 = kbase + c * KC;
            __half* xd = Xs + (c & 1) * (BATCH * XSH);
            // 512 float4, one per thread
            int row = tid >> 1;
            int seg = tid & 1;
            cp_async16(xd + row * XSH + seg * 8,
                       g_x_h + (long)row * IN_F + k0 + seg * 8);
        }
        asm volatile("cp.async.commit_group;");
    };
    auto rPf = [&](int c) {                    // weights chunk c -> stage c%4
        if (c < NCHUNK) {
            float* rd = Raw + (c & 3) * RAW_FL;
            const int k0 = c * KC;
            if (tid < 768)
                cp_async16(rd + rs0 * (NT * KC) + ri0 * 4,
                           streams[rs0] + rg0 + k0);
            if (tid < 256)
                cp_async16(rd + 2 * (NT * KC) + ri1 * 4,
                           streams[2] + rg1 + k0);
        }
        asm volatile("cp.async.commit_group;");
    };

    // Wgen(k): raw stage k%4 -> Wg[k&1]; KL with prior constants folded
    auto wgen = [&](int k) {
        const float* rb = Raw + (k & 3) * RAW_FL;
        float2 m2 = *reinterpret_cast<const float2*>(rb + 0 * NT * KC + we);
        float2 r2 = *reinterpret_cast<const float2*>(rb + 1 * NT * KC + we);
        float2 e2 = *reinterpret_cast<const float2*>(rb + 2 * NT * KC + we);
        const float mv[2] = {m2.x, m2.y};
        const float rv[2] = {r2.x, r2.y};
        const float ev[2] = {e2.x, e2.y};
        float wv[2];
#pragma unroll
        for (int q = 0; q < 2; q++) {
            float sg = __logf(1.f + __expf(rv[q]));    // softplus
            wv[q] = fmaf(sg, ev[q], mv[q]);
            klsum += fmaf(50.f, fmaf(sg, sg, mv[q] * mv[q]),
                          KL_C0 - __logf(sg));
        }
        __half2 p0 = __floats2half2_rn(wv[0], wv[1]);
        *reinterpret_cast<__half2*>(
            (__half*)(smbase + XSTG * XS_BYTES + RSTG * RAW_BYTES)
            + (k & 1) * (NT * WSH) + wrow * WSH + wk) = p0;
    };

    // ---- prologue: groups [raw0][raw1][X0][raw2]; land raw0; Wgen(0) ----
    rPf(0);
    rPf(1);
    xPf(0);
    rPf(2);
    asm volatile("cp.async.wait_group 3;");
    __syncthreads();
    wgen(0);

    for (int c = 0; c < NCHUNK; c++) {
        asm volatile("cp.async.wait_group 1;");  // X(c), raw(c+1) landed
        __syncthreads();                         // one barrier per chunk

        xPf(c + 1);                              // stage (c+1)&1
        rPf(c + 3);                              // stage (c+3)&3

        if (c + 1 < NCHUNK) wgen(c + 1);         // -> Wg[(c+1)&1], overlaps MMA

        // ---- MMA(c): A (one m16 tile) + B via ldmatrix ----
        const unsigned xa = xs_b + (c & 1) * XS_BYTES + a_off;
        unsigned a0[4];
        ldsm_x4(a0[0], a0[1], a0[2], a0[3], xa);

        const unsigned wb = wg_b + (c & 1) * WG_BYTES + b_off0;
#pragma unroll
        for (int p = 0; p < 4; p++) {
            unsigned b0, b1, b2, b3;
            ldsm_x4(b0, b1, b2, b3, wb + p * 16 * WSH * 2);
            mma_f16(acc[2 * p],     a0, b0, b1);
            mma_f16(acc[2 * p + 1], a0, b2, b3);
        }
    }

    // ---- epilogue: atomic-accumulate partial output (bias already in out) ----
    {
        int r0 = m16 + g;
#pragma unroll
        for (int nt = 0; nt < 8; nt++) {
            int col = n0 + nt * 8 + 2 * t;
            atomicAdd(&out[(long)r0 * OUT_F + col],           acc[nt][0]);
            atomicAdd(&out[(long)r0 * OUT_F + col + 1],       acc[nt][1]);
            atomicAdd(&out[(long)(r0 + 8) * OUT_F + col],     acc[nt][2]);
            atomicAdd(&out[(long)(r0 + 8) * OUT_F + col + 1], acc[nt][3]);
        }
    }

    // ---- KL reduction ----
#pragma unroll
    for (int o = 16; o; o >>= 1)
        klsum += __shfl_xor_sync(0xFFFFFFFFu, klsum, o);
    if (lane == 0) klred[warp] = klsum;
    __syncthreads();
    if (tid == 0) {
        float s = 0.f;
#pragma unroll
        for (int i = 0; i < 16; i++) s += klred[i];
        atomicAdd(klout, s);
    }
}

// ---------------------------------------------------------------------------
extern "C" void kernel_launch(void* const* d_in, const int* in_sizes, int n_in,
                              void* d_out, int out_size) {
    const float* x    = (const float*)d_in[0];
    const float* wmu  = (const float*)d_in[1];
    const float* wrho = (const float*)d_in[2];
    const float* bmu  = (const float*)d_in[3];
    const float* brho = (const float*)d_in[4];
    const float* epsw = (const float*)d_in[5];
    const float* epsb = (const float*)d_in[6];
    float* out = (float*)d_out;

    int n = BATCH * IN_F;
    if (out_size > n) n = out_size;
    vl_prep<<<(n + 255) / 256, 256>>>(x, bmu, brho, epsb, out, out_size);

    cudaFuncSetAttribute(vl_main, cudaFuncAttributeMaxDynamicSharedMemorySize,
                         SMEM_BYTES);
    vl_main<<<(OUT_F / NT) * KSPLIT, THREADS, SMEM_BYTES>>>(
        wmu, wrho, epsw, out, out + (out_size - 1));
}